// round 5
// baseline (speedup 1.0000x reference)
#include <cuda_runtime.h>
#include <cstdint>

// N = M = 8192 points, 4 components. Fully fused single kernel.
// Grid: 8 adv-blocks x 92 splits = 736 CTAs ~= 5 CTAs/SM on 148 SMs.
#define SPLITS 92
#define CHUNK 90             // per-split ori points (jn = 90 or 2 -> always even)
#define ADV_PER_BLOCK 1024
#define THREADS 256
#define T 4                  // adv points per thread
#define NMAX 8192
#define NB 8                 // adv blocks

// Graph-safe scratch: partials fully overwritten every launch; counters
// self-reset to 0 via atomicInc wrap semantics -> deterministic replays.
__device__ float g_partial[SPLITS * NMAX];
__device__ float g_blockmax[NB];
__device__ unsigned int g_cnt[NB];   // zero-init at load; wraps back to 0 each replay
__device__ unsigned int g_cnt2;      // ditto

// Struct-of-pairs ori layout: one LDS.128 -> two packed f32x2 operands.
struct __align__(16) OriPair {
    float f[12];  // bx0 bx1 | by0 by1 | bz0 bz1 | bw0 bw1 | c0 c1 | pad pad
};

__device__ __forceinline__ uint64_t ffma2(uint64_t a, uint64_t b, uint64_t c) {
    uint64_t d;
    asm("fma.rn.f32x2 %0, %1, %2, %3;" : "=l"(d) : "l"(a), "l"(b), "l"(c));
    return d;
}
__device__ __forceinline__ uint64_t pack2(float x) {
    uint64_t d;
    asm("mov.b64 %0, {%1, %1};" : "=l"(d) : "f"(x));
    return d;
}
__device__ __forceinline__ float2 unpack2(uint64_t v) {
    float2 r;
    asm("mov.b64 {%0, %1}, %2;" : "=f"(r.x), "=f"(r.y) : "l"(v));
    return r;
}

__global__ __launch_bounds__(THREADS, 5)
void hd_fused(const float* __restrict__ adv, const float* __restrict__ ori,
              float* __restrict__ out, int n, int m) {
    __shared__ OriPair sp[(CHUNK + 1) / 2];
    __shared__ int s_role;          // 1 if this CTA is last of its adv-block
    __shared__ float s_red[THREADS];

    const int tid = threadIdx.x;
    const int bx  = blockIdx.x;     // adv block
    const int j0  = blockIdx.y * CHUNK;
    const int jn  = min(CHUNK, m - j0);
    const int base = bx * ADV_PER_BLOCK + tid;

    // ---- Phase 1: partial mins for (adv block bx, ori split blockIdx.y) ----
    for (int j = tid; j < jn; j += THREADS) {
        float4 b = reinterpret_cast<const float4*>(ori)[j0 + j];
        b.w *= 0.5f;  // INTENSITY_WEIGHT
        float c = b.x * b.x + b.y * b.y + b.z * b.z + b.w * b.w;
        float* dst = sp[j >> 1].f + (j & 1);
        dst[0] = b.x; dst[2] = b.y; dst[4] = b.z; dst[6] = b.w; dst[8] = c;
    }
    __syncthreads();

    uint64_t ax[T], ay[T], az[T], aw[T];
    float a2[T], mn[T];
#pragma unroll
    for (int k = 0; k < T; k++) {
        float4 a = reinterpret_cast<const float4*>(adv)[base + k * THREADS];
        a.w *= 0.5f;
        a2[k] = a.x * a.x + a.y * a.y + a.z * a.z + a.w * a.w;
        ax[k] = pack2(-2.0f * a.x);
        ay[k] = pack2(-2.0f * a.y);
        az[k] = pack2(-2.0f * a.z);
        aw[k] = pack2(-2.0f * a.w);
        mn[k] = INFINITY;
    }

    const int np = jn >> 1;
#pragma unroll 4
    for (int p = 0; p < np; p++) {
        const ulonglong2 q0 = *reinterpret_cast<const ulonglong2*>(&sp[p].f[0]);
        const ulonglong2 q1 = *reinterpret_cast<const ulonglong2*>(&sp[p].f[4]);
        const uint64_t   cc = *reinterpret_cast<const uint64_t*>(&sp[p].f[8]);
#pragma unroll
        for (int k = 0; k < T; k++) {
            uint64_t d = ffma2(ax[k], q0.x, cc);
            d = ffma2(ay[k], q0.y, d);
            d = ffma2(az[k], q1.x, d);
            d = ffma2(aw[k], q1.y, d);
            float2 t = unpack2(d);
            mn[k] = fminf(mn[k], fminf(t.x, t.y));
        }
    }
    if (jn & 1) {   // never taken for these shapes, kept for safety
        const float* f = sp[(jn - 1) >> 1].f;
        const float bxx = f[0], byy = f[2], bzz = f[4], bww = f[6], c = f[8];
#pragma unroll
        for (int k = 0; k < T; k++) {
            float t = fmaf(unpack2(ax[k]).x, bxx, c);
            t = fmaf(unpack2(ay[k]).x, byy, t);
            t = fmaf(unpack2(az[k]).x, bzz, t);
            t = fmaf(unpack2(aw[k]).x, bww, t);
            mn[k] = fminf(mn[k], t);
        }
    }

#pragma unroll
    for (int k = 0; k < T; k++) {
        g_partial[blockIdx.y * n + base + k * THREADS] = mn[k] + a2[k];
    }

    // ---- Ticket: last CTA of this adv-block combines its splits ----
    __threadfence();
    __syncthreads();
    if (tid == 0) {
        unsigned old = atomicInc(&g_cnt[bx], SPLITS - 1);  // wraps to 0 -> replay-safe
        s_role = (old == SPLITS - 1);
    }
    __syncthreads();
    if (!s_role) return;

    // ---- Phase 2 (one CTA per adv-block): min over splits, then block max ----
    __threadfence();
    float v[T];
#pragma unroll
    for (int k = 0; k < T; k++) v[k] = INFINITY;
#pragma unroll 4
    for (int s = 0; s < SPLITS; s++) {
#pragma unroll
        for (int k = 0; k < T; k++) {
            v[k] = fminf(v[k], g_partial[s * n + base + k * THREADS]);
        }
    }
    float vmax = fmaxf(fmaxf(v[0], v[1]), fmaxf(v[2], v[3]));
    s_red[tid] = vmax;
    __syncthreads();
    for (int off = THREADS / 2; off >= 32; off >>= 1) {
        if (tid < off) s_red[tid] = fmaxf(s_red[tid], s_red[tid + off]);
        __syncthreads();
    }
    if (tid < 32) {
        float w = s_red[tid];
#pragma unroll
        for (int off = 16; off > 0; off >>= 1)
            w = fmaxf(w, __shfl_xor_sync(0xffffffffu, w, off));
        if (tid == 0) {
            g_blockmax[bx] = w;
            __threadfence();
            unsigned old2 = atomicInc(&g_cnt2, NB - 1);    // wraps -> replay-safe
            s_role = (old2 == NB - 1) ? 2 : 0;
        }
    }
    __syncthreads();
    if (s_role != 2) return;

    // ---- Phase 3 (one thread): final max over NB block maxima ----
    if (tid == 0) {
        __threadfence();
        float r = g_blockmax[0];
#pragma unroll
        for (int b = 1; b < NB; b++) r = fmaxf(r, g_blockmax[b]);
        out[0] = r;   // LOSS_WEIGHT = 1.0
    }
}

extern "C" void kernel_launch(void* const* d_in, const int* in_sizes, int n_in,
                              void* d_out, int out_size) {
    const float* adv = (const float*)d_in[0];
    const float* ori = (const float*)d_in[1];
    float* out = (float*)d_out;

    const int n = in_sizes[0] / 4;   // 8192
    const int m = in_sizes[1] / 4;   // 8192

    dim3 grid((n + ADV_PER_BLOCK - 1) / ADV_PER_BLOCK, SPLITS);
    hd_fused<<<grid, THREADS>>>(adv, ori, out, n, m);
}

// round 6
// speedup vs baseline: 1.1620x; 1.1620x over previous
#include <cuda_runtime.h>
#include <cstdint>

// N = M = 8192 points, 4 components.
// K1 grid: 8 adv-blocks x 74 splits = 592 CTAs = 4 CTAs/SM on 148 SMs (R4 config).
#define SPLITS 74
#define CHUNK 112            // per-split ori points (jn = 112 or 16 -> always even)
#define ADV_PER_BLOCK 1024
#define THREADS 256
#define T 4                  // adv points per thread
#define NMAX 8192
#define NB2 64               // combine-kernel CTAs

// Graph-safe scratch: partials fully overwritten every launch; ticket counter
// self-resets to 0 via atomicInc wrap semantics -> deterministic replays.
__device__ float g_partial[SPLITS * NMAX];
__device__ float g_blockmax[NB2];
__device__ unsigned int g_cnt2;   // zero at load; wraps back to 0 every replay

// Struct-of-pairs ori layout: one LDS.128 -> two packed f32x2 operands.
struct __align__(16) OriPair {
    float f[12];  // bx0 bx1 | by0 by1 | bz0 bz1 | bw0 bw1 | c0 c1 | pad pad
};

__device__ __forceinline__ uint64_t ffma2(uint64_t a, uint64_t b, uint64_t c) {
    uint64_t d;
    asm("fma.rn.f32x2 %0, %1, %2, %3;" : "=l"(d) : "l"(a), "l"(b), "l"(c));
    return d;
}
__device__ __forceinline__ uint64_t pack2(float x) {
    uint64_t d;
    asm("mov.b64 %0, {%1, %1};" : "=l"(d) : "f"(x));
    return d;
}
__device__ __forceinline__ float2 unpack2(uint64_t v) {
    float2 r;
    asm("mov.b64 {%0, %1}, %2;" : "=f"(r.x), "=f"(r.y) : "l"(v));
    return r;
}

// Kernel 1 (unchanged from R4 - measured 14.8us): per (adv block, ori split)
// partial mins with packed f32x2 math.
__global__ __launch_bounds__(THREADS)
void hd_partial_min(const float* __restrict__ adv, const float* __restrict__ ori,
                    int n, int m) {
    __shared__ OriPair sp[(CHUNK + 1) / 2];

    const int tid = threadIdx.x;
    const int j0  = blockIdx.y * CHUNK;
    const int jn  = min(CHUNK, m - j0);

    for (int j = tid; j < jn; j += THREADS) {
        float4 b = reinterpret_cast<const float4*>(ori)[j0 + j];
        b.w *= 0.5f;  // INTENSITY_WEIGHT
        float c = b.x * b.x + b.y * b.y + b.z * b.z + b.w * b.w;
        float* dst = sp[j >> 1].f + (j & 1);
        dst[0] = b.x; dst[2] = b.y; dst[4] = b.z; dst[6] = b.w; dst[8] = c;
    }
    __syncthreads();

    uint64_t ax[T], ay[T], az[T], aw[T];
    float a2[T], mn[T];
    const int base = blockIdx.x * ADV_PER_BLOCK + tid;
#pragma unroll
    for (int k = 0; k < T; k++) {
        float4 a = reinterpret_cast<const float4*>(adv)[base + k * THREADS];
        a.w *= 0.5f;
        a2[k] = a.x * a.x + a.y * a.y + a.z * a.z + a.w * a.w;
        ax[k] = pack2(-2.0f * a.x);
        ay[k] = pack2(-2.0f * a.y);
        az[k] = pack2(-2.0f * a.z);
        aw[k] = pack2(-2.0f * a.w);
        mn[k] = INFINITY;
    }

    const int np = jn >> 1;   // 56 or 8 -> divisible by 4
#pragma unroll 4
    for (int p = 0; p < np; p++) {
        const ulonglong2 q0 = *reinterpret_cast<const ulonglong2*>(&sp[p].f[0]);
        const ulonglong2 q1 = *reinterpret_cast<const ulonglong2*>(&sp[p].f[4]);
        const uint64_t   cc = *reinterpret_cast<const uint64_t*>(&sp[p].f[8]);
#pragma unroll
        for (int k = 0; k < T; k++) {
            uint64_t d = ffma2(ax[k], q0.x, cc);
            d = ffma2(ay[k], q0.y, d);
            d = ffma2(az[k], q1.x, d);
            d = ffma2(aw[k], q1.y, d);
            float2 t = unpack2(d);
            mn[k] = fminf(mn[k], fminf(t.x, t.y));
        }
    }
    if (jn & 1) {   // never taken for these shapes, kept for safety
        const float* f = sp[(jn - 1) >> 1].f;
        const float bxx = f[0], byy = f[2], bzz = f[4], bww = f[6], c = f[8];
#pragma unroll
        for (int k = 0; k < T; k++) {
            float t = fmaf(unpack2(ax[k]).x, bxx, c);
            t = fmaf(unpack2(ay[k]).x, byy, t);
            t = fmaf(unpack2(az[k]).x, bzz, t);
            t = fmaf(unpack2(aw[k]).x, bww, t);
            mn[k] = fminf(mn[k], t);
        }
    }

#pragma unroll
    for (int k = 0; k < T; k++) {
        g_partial[blockIdx.y * n + base + k * THREADS] = mn[k] + a2[k];
    }
}

// Kernel 2 (fused combine + final): min over splits per point, block max,
// last CTA (atomicInc ticket, wrap-reset) reduces 64 block maxima -> out[0].
__global__ __launch_bounds__(128)
void hd_combine_final(float* __restrict__ out, int n) {
    __shared__ float sm[128];
    __shared__ int s_last;

    const int tid = threadIdx.x;
    const int i = blockIdx.x * 128 + tid;

    float v = INFINITY;
#pragma unroll 4
    for (int s = 0; s < SPLITS; s++) {
        v = fminf(v, g_partial[s * n + i]);
    }
    sm[tid] = v;
    __syncthreads();
    for (int off = 64; off >= 32; off >>= 1) {
        if (tid < off) sm[tid] = fmaxf(sm[tid], sm[tid + off]);
        __syncthreads();
    }
    if (tid < 32) {
        float w = sm[tid];
#pragma unroll
        for (int off = 16; off > 0; off >>= 1)
            w = fmaxf(w, __shfl_xor_sync(0xffffffffu, w, off));
        if (tid == 0) {
            g_blockmax[blockIdx.x] = w;
            __threadfence();
            unsigned old = atomicInc(&g_cnt2, NB2 - 1);  // wraps to 0 -> replay-safe
            s_last = (old == NB2 - 1);
        }
    }
    __syncthreads();
    if (!s_last) return;

    // Last CTA: reduce the 64 block maxima.
    if (tid < 32) {
        __threadfence();
        float w = fmaxf(g_blockmax[tid], g_blockmax[tid + 32]);
#pragma unroll
        for (int off = 16; off > 0; off >>= 1)
            w = fmaxf(w, __shfl_xor_sync(0xffffffffu, w, off));
        if (tid == 0) out[0] = w;   // LOSS_WEIGHT = 1.0
    }
}

extern "C" void kernel_launch(void* const* d_in, const int* in_sizes, int n_in,
                              void* d_out, int out_size) {
    const float* adv = (const float*)d_in[0];
    const float* ori = (const float*)d_in[1];
    float* out = (float*)d_out;

    const int n = in_sizes[0] / 4;   // 8192
    const int m = in_sizes[1] / 4;   // 8192

    dim3 grid1((n + ADV_PER_BLOCK - 1) / ADV_PER_BLOCK, SPLITS);
    hd_partial_min<<<grid1, THREADS>>>(adv, ori, n, m);
    hd_combine_final<<<NB2, 128>>>(out, n);
}

// round 7
// speedup vs baseline: 1.2653x; 1.0889x over previous
#include <cuda_runtime.h>
#include <cstdint>

// N = M = 8192 points, 4 components.
// K1 grid: 8 adv-blocks x 74 splits = 592 CTAs = 4 CTAs/SM on 148 SMs (R4 config).
#define SPLITS 74
#define CHUNK 112            // per-split ori points (jn = 112 or 16 -> always even)
#define ADV_PER_BLOCK 1024
#define THREADS 256
#define T 4                  // adv points per thread
#define NMAX 8192
#define NB2 64               // combine-kernel CTAs

// Graph-safe scratch: fully overwritten every launch.
__device__ float g_partial[SPLITS * NMAX];
__device__ float g_blockmax[NB2];

// Struct-of-pairs ori layout: one LDS.128 -> two packed f32x2 operands.
struct __align__(16) OriPair {
    float f[12];  // bx0 bx1 | by0 by1 | bz0 bz1 | bw0 bw1 | c0 c1 | pad pad
};

__device__ __forceinline__ uint64_t ffma2(uint64_t a, uint64_t b, uint64_t c) {
    uint64_t d;
    asm("fma.rn.f32x2 %0, %1, %2, %3;" : "=l"(d) : "l"(a), "l"(b), "l"(c));
    return d;
}
__device__ __forceinline__ uint64_t pack2(float x) {
    uint64_t d;
    asm("mov.b64 %0, {%1, %1};" : "=l"(d) : "f"(x));
    return d;
}
__device__ __forceinline__ float2 unpack2(uint64_t v) {
    float2 r;
    asm("mov.b64 {%0, %1}, %2;" : "=f"(r.x), "=f"(r.y) : "l"(v));
    return r;
}

// Kernel 1 (unchanged from R4 - measured 14.8us): per (adv block, ori split)
// partial mins with packed f32x2 math.
__global__ __launch_bounds__(THREADS)
void hd_partial_min(const float* __restrict__ adv, const float* __restrict__ ori,
                    int n, int m) {
    __shared__ OriPair sp[(CHUNK + 1) / 2];

    const int tid = threadIdx.x;
    const int j0  = blockIdx.y * CHUNK;
    const int jn  = min(CHUNK, m - j0);

    for (int j = tid; j < jn; j += THREADS) {
        float4 b = reinterpret_cast<const float4*>(ori)[j0 + j];
        b.w *= 0.5f;  // INTENSITY_WEIGHT
        float c = b.x * b.x + b.y * b.y + b.z * b.z + b.w * b.w;
        float* dst = sp[j >> 1].f + (j & 1);
        dst[0] = b.x; dst[2] = b.y; dst[4] = b.z; dst[6] = b.w; dst[8] = c;
    }
    __syncthreads();

    uint64_t ax[T], ay[T], az[T], aw[T];
    float a2[T], mn[T];
    const int base = blockIdx.x * ADV_PER_BLOCK + tid;
#pragma unroll
    for (int k = 0; k < T; k++) {
        float4 a = reinterpret_cast<const float4*>(adv)[base + k * THREADS];
        a.w *= 0.5f;
        a2[k] = a.x * a.x + a.y * a.y + a.z * a.z + a.w * a.w;
        ax[k] = pack2(-2.0f * a.x);
        ay[k] = pack2(-2.0f * a.y);
        az[k] = pack2(-2.0f * a.z);
        aw[k] = pack2(-2.0f * a.w);
        mn[k] = INFINITY;
    }

    const int np = jn >> 1;   // 56 or 8 -> divisible by 4
#pragma unroll 4
    for (int p = 0; p < np; p++) {
        const ulonglong2 q0 = *reinterpret_cast<const ulonglong2*>(&sp[p].f[0]);
        const ulonglong2 q1 = *reinterpret_cast<const ulonglong2*>(&sp[p].f[4]);
        const uint64_t   cc = *reinterpret_cast<const uint64_t*>(&sp[p].f[8]);
#pragma unroll
        for (int k = 0; k < T; k++) {
            uint64_t d = ffma2(ax[k], q0.x, cc);
            d = ffma2(ay[k], q0.y, d);
            d = ffma2(az[k], q1.x, d);
            d = ffma2(aw[k], q1.y, d);
            float2 t = unpack2(d);
            mn[k] = fminf(mn[k], fminf(t.x, t.y));
        }
    }
    if (jn & 1) {   // never taken for these shapes, kept for safety
        const float* f = sp[(jn - 1) >> 1].f;
        const float bxx = f[0], byy = f[2], bzz = f[4], bww = f[6], c = f[8];
#pragma unroll
        for (int k = 0; k < T; k++) {
            float t = fmaf(unpack2(ax[k]).x, bxx, c);
            t = fmaf(unpack2(ay[k]).x, byy, t);
            t = fmaf(unpack2(az[k]).x, bzz, t);
            t = fmaf(unpack2(aw[k]).x, bww, t);
            mn[k] = fminf(mn[k], t);
        }
    }

#pragma unroll
    for (int k = 0; k < T; k++) {
        g_partial[blockIdx.y * n + base + k * THREADS] = mn[k] + a2[k];
    }
}

// Kernel 2 (wide combine): 64 CTAs x 512 threads. Each CTA owns 128 points;
// 4 split-groups per point (19/19/19/17 splits) -> ~19 independent coalesced
// loads per thread (one latency round), smem min across groups, then block max.
__global__ __launch_bounds__(512)
void hd_combine(int n) {
    __shared__ float red[512];

    const int tid = threadIdx.x;
    const int p_local = tid & 127;
    const int sg = tid >> 7;                 // split group 0..3
    const int i = blockIdx.x * 128 + p_local;

    const int s0 = sg * 19;
    const int s1 = (s0 + 19 < SPLITS) ? s0 + 19 : SPLITS;

    float v = INFINITY;
#pragma unroll 19
    for (int s = s0; s < s1; s++) {
        v = fminf(v, g_partial[s * n + i]);
    }
    red[tid] = v;
    __syncthreads();

    if (tid < 128) {
        red[tid] = fminf(fminf(red[tid], red[tid + 128]),
                         fminf(red[tid + 256], red[tid + 384]));
    }
    __syncthreads();
    if (tid < 64) red[tid] = fmaxf(red[tid], red[tid + 64]);
    __syncthreads();
    if (tid < 32) {
        float w = fmaxf(red[tid], red[tid + 32]);
#pragma unroll
        for (int off = 16; off > 0; off >>= 1)
            w = fmaxf(w, __shfl_xor_sync(0xffffffffu, w, off));
        if (tid == 0) g_blockmax[blockIdx.x] = w;
    }
}

// Kernel 3: reduce 64 block maxima -> out[0]. One warp.
__global__ void hd_final(float* __restrict__ out) {
    float v = fmaxf(g_blockmax[threadIdx.x], g_blockmax[threadIdx.x + 32]);
#pragma unroll
    for (int off = 16; off > 0; off >>= 1) {
        v = fmaxf(v, __shfl_xor_sync(0xffffffffu, v, off));
    }
    if (threadIdx.x == 0) out[0] = v;   // LOSS_WEIGHT = 1.0
}

extern "C" void kernel_launch(void* const* d_in, const int* in_sizes, int n_in,
                              void* d_out, int out_size) {
    const float* adv = (const float*)d_in[0];
    const float* ori = (const float*)d_in[1];
    float* out = (float*)d_out;

    const int n = in_sizes[0] / 4;   // 8192
    const int m = in_sizes[1] / 4;   // 8192

    dim3 grid1((n + ADV_PER_BLOCK - 1) / ADV_PER_BLOCK, SPLITS);
    hd_partial_min<<<grid1, THREADS>>>(adv, ori, n, m);
    hd_combine<<<NB2, 512>>>(n);
    hd_final<<<1, 32>>>(out);
}

// round 8
// speedup vs baseline: 1.4257x; 1.1268x over previous
#include <cuda_runtime.h>
#include <cstdint>

// N = M = 8192 points, 4 components.
// K1 grid: 8 adv-blocks x 74 splits = 592 CTAs = 4 CTAs/SM on 148 SMs.
#define SPLITS 74
#define CHUNK 112            // per-split ori points (jn = 112 or 16 -> always even)
#define ADV_PER_BLOCK 1024
#define THREADS 256
#define T 4                  // adv points per thread
#define NMAX 8192

// Per-point order-inverted min keys. key = 0x7FFFFFFF - float_bits(v), v >= 0.
// atomicMax(key) == atomicMin(v). Identity = 0 == zero-init state == the value
// K2 resets to after consuming -> deterministic across graph replays, no init
// kernel needed.
__device__ unsigned int g_minkey[NMAX];

// Struct-of-pairs ori layout: one LDS.128 -> two packed f32x2 operands.
struct __align__(16) OriPair {
    float f[12];  // bx0 bx1 | by0 by1 | bz0 bz1 | bw0 bw1 | c0 c1 | pad pad
};

__device__ __forceinline__ uint64_t ffma2(uint64_t a, uint64_t b, uint64_t c) {
    uint64_t d;
    asm("fma.rn.f32x2 %0, %1, %2, %3;" : "=l"(d) : "l"(a), "l"(b), "l"(c));
    return d;
}
__device__ __forceinline__ uint64_t pack2(float x) {
    uint64_t d;
    asm("mov.b64 %0, {%1, %1};" : "=l"(d) : "f"(x));
    return d;
}
__device__ __forceinline__ float2 unpack2(uint64_t v) {
    float2 r;
    asm("mov.b64 {%0, %1}, %2;" : "=f"(r.x), "=f"(r.y) : "l"(v));
    return r;
}

// Kernel 1: per (adv block, ori split) partial mins with packed f32x2 math
// (R4 mainloop, measured 14.8us), epilogue = REDG.MAX of inverted key instead
// of writing a partials array.
__global__ __launch_bounds__(THREADS)
void hd_partial_min(const float* __restrict__ adv, const float* __restrict__ ori,
                    int n, int m) {
    __shared__ OriPair sp[(CHUNK + 1) / 2];

    const int tid = threadIdx.x;
    const int j0  = blockIdx.y * CHUNK;
    const int jn  = min(CHUNK, m - j0);

    for (int j = tid; j < jn; j += THREADS) {
        float4 b = reinterpret_cast<const float4*>(ori)[j0 + j];
        b.w *= 0.5f;  // INTENSITY_WEIGHT
        float c = b.x * b.x + b.y * b.y + b.z * b.z + b.w * b.w;
        float* dst = sp[j >> 1].f + (j & 1);
        dst[0] = b.x; dst[2] = b.y; dst[4] = b.z; dst[6] = b.w; dst[8] = c;
    }
    __syncthreads();

    uint64_t ax[T], ay[T], az[T], aw[T];
    float a2[T], mn[T];
    const int base = blockIdx.x * ADV_PER_BLOCK + tid;
#pragma unroll
    for (int k = 0; k < T; k++) {
        float4 a = reinterpret_cast<const float4*>(adv)[base + k * THREADS];
        a.w *= 0.5f;
        a2[k] = a.x * a.x + a.y * a.y + a.z * a.z + a.w * a.w;
        ax[k] = pack2(-2.0f * a.x);
        ay[k] = pack2(-2.0f * a.y);
        az[k] = pack2(-2.0f * a.z);
        aw[k] = pack2(-2.0f * a.w);
        mn[k] = INFINITY;
    }

    const int np = jn >> 1;   // 56 or 8 -> divisible by 4
#pragma unroll 4
    for (int p = 0; p < np; p++) {
        const ulonglong2 q0 = *reinterpret_cast<const ulonglong2*>(&sp[p].f[0]);
        const ulonglong2 q1 = *reinterpret_cast<const ulonglong2*>(&sp[p].f[4]);
        const uint64_t   cc = *reinterpret_cast<const uint64_t*>(&sp[p].f[8]);
#pragma unroll
        for (int k = 0; k < T; k++) {
            uint64_t d = ffma2(ax[k], q0.x, cc);
            d = ffma2(ay[k], q0.y, d);
            d = ffma2(az[k], q1.x, d);
            d = ffma2(aw[k], q1.y, d);
            float2 t = unpack2(d);
            mn[k] = fminf(mn[k], fminf(t.x, t.y));
        }
    }
    if (jn & 1) {   // never taken for these shapes, kept for safety
        const float* f = sp[(jn - 1) >> 1].f;
        const float bxx = f[0], byy = f[2], bzz = f[4], bww = f[6], c = f[8];
#pragma unroll
        for (int k = 0; k < T; k++) {
            float t = fmaf(unpack2(ax[k]).x, bxx, c);
            t = fmaf(unpack2(ay[k]).x, byy, t);
            t = fmaf(unpack2(az[k]).x, bzz, t);
            t = fmaf(unpack2(aw[k]).x, bww, t);
            mn[k] = fminf(mn[k], t);
        }
    }

    // Epilogue: clamp to >=0 (squared distance; clamps only FP-cancellation
    // negatives ~1e-7 which cannot be the global max), invert, REDG.MAX.
#pragma unroll
    for (int k = 0; k < T; k++) {
        float v = fmaxf(mn[k] + a2[k], 0.0f);
        unsigned int key = 0x7FFFFFFFu - __float_as_uint(v);
        atomicMax(&g_minkey[base + k * THREADS], key);   // no return -> REDG
    }
}

// Kernel 2: one CTA. Consume g_minkey (decode + max-reduce), reset it to 0
// for the next replay (each thread resets exactly the slots it read -> no
// cross-thread hazard), write the final scalar.
__global__ __launch_bounds__(1024)
void hd_final(float* __restrict__ out, int n) {
    __shared__ float red[1024];
    const int tid = threadIdx.x;

    const int nq = n / 4;   // 2048 uint4
    float v = 0.0f;         // all decoded values are >= 0
    for (int q = tid; q < nq; q += 1024) {   // 2 iterations
        uint4 s = reinterpret_cast<uint4*>(g_minkey)[q];
        reinterpret_cast<uint4*>(g_minkey)[q] = make_uint4(0u, 0u, 0u, 0u);
        v = fmaxf(v, __uint_as_float(0x7FFFFFFFu - s.x));
        v = fmaxf(v, __uint_as_float(0x7FFFFFFFu - s.y));
        v = fmaxf(v, __uint_as_float(0x7FFFFFFFu - s.z));
        v = fmaxf(v, __uint_as_float(0x7FFFFFFFu - s.w));
    }
    red[tid] = v;
    __syncthreads();
    for (int off = 512; off >= 32; off >>= 1) {
        if (tid < off) red[tid] = fmaxf(red[tid], red[tid + off]);
        __syncthreads();
    }
    if (tid < 32) {
        float w = red[tid];
#pragma unroll
        for (int off = 16; off > 0; off >>= 1)
            w = fmaxf(w, __shfl_xor_sync(0xffffffffu, w, off));
        if (tid == 0) out[0] = w;   // LOSS_WEIGHT = 1.0
    }
}

extern "C" void kernel_launch(void* const* d_in, const int* in_sizes, int n_in,
                              void* d_out, int out_size) {
    const float* adv = (const float*)d_in[0];
    const float* ori = (const float*)d_in[1];
    float* out = (float*)d_out;

    const int n = in_sizes[0] / 4;   // 8192
    const int m = in_sizes[1] / 4;   // 8192

    dim3 grid1((n + ADV_PER_BLOCK - 1) / ADV_PER_BLOCK, SPLITS);
    hd_partial_min<<<grid1, THREADS>>>(adv, ori, n, m);
    hd_final<<<1, 1024>>>(out, n);
}